// round 5
// baseline (speedup 1.0000x reference)
#include <cuda_runtime.h>
#include <cuda_bf16.h>
#include <cstdint>
#include <cstddef>

#define NB 8
#define NN 2048
#define FD 128

// ---------------- device scratch (no cudaMalloc allowed) ----------------
__device__ float g_dis[NB * NN];
__device__ __nv_bfloat16 g_Ahi[(size_t)NB * NN * NN];  // hi(dis[n]*adj[n,m])
__device__ __nv_bfloat16 g_Alo[(size_t)NB * NN * NN];  // lo residue
__device__ __nv_bfloat16 g_Hhi[NB * FD * NN];          // hi(dis[m]*lrelu(XW+b)), [b][f][m]
__device__ __nv_bfloat16 g_Hlo[NB * FD * NN];
__device__ float g_X1[NB * NN * FD];
__device__ float g_X2[NB * NN * FD];
__device__ float g_Wr[3 * FD * FD];                    // tf32-rounded weights [k][n]

// ---------------- helpers ----------------
__device__ __forceinline__ uint32_t cvt_rna(float x) {
    uint32_t r;
    asm("cvt.rna.tf32.f32 %0, %1;" : "=r"(r) : "f"(x));
    return r;
}
__device__ __forceinline__ void cp16(uint32_t smem_dst, const void* gsrc) {
    asm volatile("cp.async.cg.shared.global [%0], [%1], 16;" :: "r"(smem_dst), "l"(gsrc));
}
#define SWZ64(o) ((o) ^ (((o) >> 3) & 0x30))

#define LDSM4(R, a) \
    asm volatile("ldmatrix.sync.aligned.m8n8.x4.shared.b16 {%0,%1,%2,%3}, [%4];" \
        : "=r"((R)[0]), "=r"((R)[1]), "=r"((R)[2]), "=r"((R)[3]) : "r"(a))

__device__ __forceinline__ void mma_bf16(float* c, const uint32_t* a, const uint32_t* b) {
    asm volatile(
        "mma.sync.aligned.m16n8k16.row.col.f32.bf16.bf16.f32 "
        "{%0,%1,%2,%3}, {%4,%5,%6,%7}, {%8,%9}, {%0,%1,%2,%3};"
        : "+f"(c[0]), "+f"(c[1]), "+f"(c[2]), "+f"(c[3])
        : "r"(a[0]), "r"(a[1]), "r"(a[2]), "r"(a[3]), "r"(b[0]), "r"(b[1]));
}
__device__ __forceinline__ void mma8(float* c, const uint32_t* a, const uint32_t* b) {
    asm volatile(
        "mma.sync.aligned.m16n8k8.row.col.f32.tf32.tf32.f32 "
        "{%0,%1,%2,%3}, {%4,%5,%6,%7}, {%8,%9}, {%0,%1,%2,%3};"
        : "+f"(c[0]), "+f"(c[1]), "+f"(c[2]), "+f"(c[3])
        : "r"(a[0]), "r"(a[1]), "r"(a[2]), "r"(a[3]), "r"(b[0]), "r"(b[1]));
}

// ---------------- prep: rowsum -> dis -> write hi/lo bf16 of dis*adj ----------------
__global__ void k_prep(const float* __restrict__ adj) {
    __shared__ float red[8];
    __shared__ float sdis;
    int row = blockIdx.x;                  // global row b*NN+n
    const float4* p = (const float4*)(adj + (size_t)row * NN);
    float s = 0.f;
    for (int i = threadIdx.x; i < NN / 4; i += 256) {
        float4 v = p[i];
        s += (v.x + v.y) + (v.z + v.w);
    }
    #pragma unroll
    for (int o = 16; o > 0; o >>= 1) s += __shfl_xor_sync(0xffffffffu, s, o);
    if ((threadIdx.x & 31) == 0) red[threadIdx.x >> 5] = s;
    __syncthreads();
    if (threadIdx.x < 8) {
        s = red[threadIdx.x];
        #pragma unroll
        for (int o = 4; o > 0; o >>= 1) s += __shfl_xor_sync(0xffu, s, o);
        if (threadIdx.x == 0) {
            float d = (s > 0.f) ? rsqrtf(s) : 0.f;
            g_dis[row] = d;
            sdis = d;
        }
    }
    __syncthreads();
    float d = sdis;
    __nv_bfloat162* oh = (__nv_bfloat162*)(g_Ahi + (size_t)row * NN);
    __nv_bfloat162* ol = (__nv_bfloat162*)(g_Alo + (size_t)row * NN);
    for (int i = threadIdx.x; i < NN / 4; i += 256) {
        float4 v = p[i];
        float f[4] = {v.x * d, v.y * d, v.z * d, v.w * d};
        __nv_bfloat16 h[4], l[4];
        #pragma unroll
        for (int q = 0; q < 4; q++) {
            h[q] = __float2bfloat16_rn(f[q]);
            l[q] = __float2bfloat16_rn(f[q] - __bfloat162float(h[q]));
        }
        oh[2 * i]     = __halves2bfloat162(h[0], h[1]);
        oh[2 * i + 1] = __halves2bfloat162(h[2], h[3]);
        ol[2 * i]     = __halves2bfloat162(l[0], l[1]);
        ol[2 * i + 1] = __halves2bfloat162(l[2], l[3]);
    }
}

__global__ void k_roundW(const float* __restrict__ W1, const float* __restrict__ W2,
                         const float* __restrict__ W3) {
    int i = blockIdx.x * 256 + threadIdx.x;
    const float* W = (i < FD * FD) ? W1 : (i < 2 * FD * FD ? W2 : W3);
    int j = i & (FD * FD - 1);
    g_Wr[i] = __uint_as_float(cvt_rna(W[j]));
}

// ---------------- small GEMM (tf32 mma.sync): H = dis*lrelu(X@W+b) -> hi/lo bf16, transposed ----
#define KC 32
#define SSTG 4
#define APAD 36
#define BPAD 136
#define A_TILE_F (128 * APAD)
#define B_TILE_F (KC * BPAD)
#define STAGE_F  (A_TILE_F + B_TILE_F)
#define SMALL_SMEM (SSTG * STAGE_F * 4)
#define NT 512

__global__ __launch_bounds__(NT, 1) void k_small(
    const float* __restrict__ Xext, const float* __restrict__ bias, int layer)
{
    extern __shared__ float sm[];
    int tid = threadIdx.x, lane = tid & 31, warp = tid >> 5;
    int warpM = (warp & 3) * 32, warpN = (warp >> 2) * 32;
    int grow = blockIdx.x * 128;
    const float* Xin = (layer == 0) ? Xext : (layer == 1 ? g_X1 : g_X2);
    const float* A = Xin + (size_t)grow * FD;
    const float* B = g_Wr + layer * FD * FD;

    float acc[2][4][4];
    #pragma unroll
    for (int mt = 0; mt < 2; mt++)
        #pragma unroll
        for (int nt = 0; nt < 4; nt++)
            #pragma unroll
            for (int i = 0; i < 4; i++) acc[mt][nt][i] = 0.f;

    auto issue = [&](int chunk) {
        float* as = sm + (chunk % SSTG) * STAGE_F;
        float* bs = as + A_TILE_F;
        uint32_t as_u = (uint32_t)__cvta_generic_to_shared(as);
        uint32_t bs_u = (uint32_t)__cvta_generic_to_shared(bs);
        int kbase = chunk * KC;
        #pragma unroll
        for (int j = 0; j < 2; j++) {
            int i = tid + NT * j;
            int r = i >> 3, c = (i & 7) << 2;
            cp16(as_u + (uint32_t)(r * APAD + c) * 4, A + (size_t)r * FD + kbase + c);
        }
        #pragma unroll
        for (int j = 0; j < 2; j++) {
            int i = tid + NT * j;
            int k = i >> 5, c = (i & 31) << 2;
            cp16(bs_u + (uint32_t)(k * BPAD + c) * 4, B + (size_t)(kbase + k) * FD + c);
        }
        asm volatile("cp.async.commit_group;");
    };

    int nch = FD / KC;
    #pragma unroll
    for (int p = 0; p < SSTG - 1; p++)
        if (p < nch) issue(p);

    for (int ch = 0; ch < nch; ch++) {
        asm volatile("cp.async.wait_group %0;" :: "n"(SSTG - 2));
        __syncthreads();
        if (ch + SSTG - 1 < nch) issue(ch + SSTG - 1);

        float* as = sm + (ch % SSTG) * STAGE_F;
        float* bs = as + A_TILE_F;
        #pragma unroll
        for (int kk = 0; kk < 4; kk++) {
            int kof = kk * 8;
            uint32_t af[2][4];
            uint32_t bf[4][2];
            #pragma unroll
            for (int mt = 0; mt < 2; mt++) {
                int r0 = warpM + mt * 16 + (lane >> 2);
                int kc = kof + (lane & 3);
                af[mt][0] = cvt_rna(as[r0 * APAD + kc]);
                af[mt][1] = cvt_rna(as[(r0 + 8) * APAD + kc]);
                af[mt][2] = cvt_rna(as[r0 * APAD + kc + 4]);
                af[mt][3] = cvt_rna(as[(r0 + 8) * APAD + kc + 4]);
            }
            #pragma unroll
            for (int nt = 0; nt < 4; nt++) {
                int nc = warpN + nt * 8 + (lane >> 2);
                int kr = kof + (lane & 3);
                bf[nt][0] = __float_as_uint(bs[kr * BPAD + nc]);
                bf[nt][1] = __float_as_uint(bs[(kr + 4) * BPAD + nc]);
            }
            #pragma unroll
            for (int mt = 0; mt < 2; mt++)
                #pragma unroll
                for (int nt = 0; nt < 4; nt++)
                    mma8(acc[mt][nt], af[mt], bf[nt]);
        }
    }

    // epilogue: lrelu+bias, *dis, split hi/lo bf16, store transposed [b][f][m]
    #pragma unroll
    for (int mt = 0; mt < 2; mt++) {
        #pragma unroll
        for (int nt = 0; nt < 4; nt++) {
            int r0 = grow + warpM + mt * 16 + (lane >> 2);
            int n0 = warpN + nt * 8 + 2 * (lane & 3);
            #pragma unroll
            for (int i = 0; i < 4; i++) {
                int r = r0 + ((i >= 2) ? 8 : 0);
                int n = n0 + (i & 1);
                float v = acc[mt][nt][i];
                v += bias[n];
                v = (v > 0.f) ? v : 0.01f * v;
                v *= g_dis[r];
                int b = r >> 11, m = r & (NN - 1);
                size_t idx = ((size_t)b * FD + n) * NN + m;
                __nv_bfloat16 h = __float2bfloat16_rn(v);
                g_Hhi[idx] = h;
                g_Hlo[idx] = __float2bfloat16_rn(v - __bfloat162float(h));
            }
        }
    }
}

// ---------------- big GEMM (bf16 3-split, ldmatrix): out = A' @ Hs (+resid) ----------------
#define KCB 32
#define BSTG 3
#define TILE_B 8192                 // 128 rows x 64B, SW64-swizzled
#define STAGE_B (4 * TILE_B)        // Ahi, Alo, Bhi, Blo = 32 KB
#define BIG_SMEM (BSTG * STAGE_B)   // 98304

__global__ __launch_bounds__(256, 1) void k_big(float* __restrict__ outext, int layer)
{
    extern __shared__ char smc[];
    uint32_t smb = (uint32_t)__cvta_generic_to_shared(smc);
    int tid = threadIdx.x, lane = tid & 31, warp = tid >> 5;
    int warpM = (warp & 3) * 32, warpN = (warp >> 2) * 64;
    int b = blockIdx.y;
    int grow = b * NN + blockIdx.x * 128;

    const __nv_bfloat16* Ah = g_Ahi + (size_t)grow * NN;
    const __nv_bfloat16* Al = g_Alo + (size_t)grow * NN;
    const __nv_bfloat16* Bh = g_Hhi + (size_t)b * FD * NN;
    const __nv_bfloat16* Bl = g_Hlo + (size_t)b * FD * NN;
    float* C = (layer == 0) ? g_X1 : (layer == 1 ? g_X2 : outext);
    const float* resid = (layer == 1) ? g_X1 : nullptr;

    float acc[2][8][4];
    #pragma unroll
    for (int mt = 0; mt < 2; mt++)
        #pragma unroll
        for (int nt = 0; nt < 8; nt++)
            #pragma unroll
            for (int i = 0; i < 4; i++) acc[mt][nt][i] = 0.f;

    auto issue = [&](int ch) {
        uint32_t base = smb + (ch % BSTG) * STAGE_B;
        int kb = ch * KCB;
        #pragma unroll
        for (int j = 0; j < 2; j++) {
            int i = tid + 256 * j;
            int r = i >> 2, c = i & 3;               // row 0..127, 16B seg 0..3
            uint32_t d = SWZ64((uint32_t)(r * 64 + c * 16));
            size_t so = (size_t)r * NN + kb;
            cp16(base + d,              (const char*)(Ah + so) + c * 16);
            cp16(base + TILE_B + d,     (const char*)(Al + so) + c * 16);
            cp16(base + 2 * TILE_B + d, (const char*)(Bh + so) + c * 16);
            cp16(base + 3 * TILE_B + d, (const char*)(Bl + so) + c * 16);
        }
        asm volatile("cp.async.commit_group;");
    };

    const int nch = NN / KCB;   // 64
    issue(0);
    issue(1);

    for (int ch = 0; ch < nch; ch++) {
        asm volatile("cp.async.wait_group 1;");
        __syncthreads();
        if (ch + 2 < nch) issue(ch + 2);
        uint32_t base = smb + (ch % BSTG) * STAGE_B;

        #pragma unroll
        for (int s = 0; s < 2; s++) {               // two K=16 steps per chunk
            int mat = lane >> 3;
            uint32_t ah[2][4], al[2][4];
            #pragma unroll
            for (int mt = 0; mt < 2; mt++) {
                int row = warpM + mt * 16 + ((mat & 1) << 3) + (lane & 7);
                uint32_t col = (uint32_t)(s * 32 + ((mat >> 1) << 4));
                uint32_t ad = base + SWZ64((uint32_t)(row * 64) + col);
                LDSM4(ah[mt], ad);
                LDSM4(al[mt], ad + TILE_B);
            }
            uint32_t bh[8][2], bl[8][2];
            #pragma unroll
            for (int p = 0; p < 4; p++) {
                int nrow = warpN + (p * 2 + (mat >> 1)) * 8 + (lane & 7);
                uint32_t col = (uint32_t)(s * 32 + ((mat & 1) << 4));
                uint32_t bd = base + 2 * TILE_B + SWZ64((uint32_t)(nrow * 64) + col);
                uint32_t t[4];
                LDSM4(t, bd);
                bh[2 * p][0] = t[0]; bh[2 * p][1] = t[1];
                bh[2 * p + 1][0] = t[2]; bh[2 * p + 1][1] = t[3];
                LDSM4(t, bd + TILE_B);
                bl[2 * p][0] = t[0]; bl[2 * p][1] = t[1];
                bl[2 * p + 1][0] = t[2]; bl[2 * p + 1][1] = t[3];
            }
            #pragma unroll
            for (int mt = 0; mt < 2; mt++)
                #pragma unroll
                for (int nt = 0; nt < 8; nt++) {
                    mma_bf16(acc[mt][nt], ah[mt], bh[nt]);
                    mma_bf16(acc[mt][nt], ah[mt], bl[nt]);
                    mma_bf16(acc[mt][nt], al[mt], bh[nt]);
                }
        }
    }

    // epilogue (dis already folded into A'); +residual on layer 1
    #pragma unroll
    for (int mt = 0; mt < 2; mt++) {
        #pragma unroll
        for (int nt = 0; nt < 8; nt++) {
            int r0 = grow + warpM + mt * 16 + (lane >> 2);
            int n = warpN + nt * 8 + 2 * (lane & 3);
            #pragma unroll
            for (int half = 0; half < 2; half++) {
                int r = r0 + half * 8;
                float2 v;
                v.x = acc[mt][nt][half * 2 + 0];
                v.y = acc[mt][nt][half * 2 + 1];
                if (resid) {
                    float2 rv = *(const float2*)(resid + (size_t)r * FD + n);
                    v.x += rv.x; v.y += rv.y;
                }
                *(float2*)(C + (size_t)r * FD + n) = v;
            }
        }
    }
}

// ---------------- launch ----------------
extern "C" void kernel_launch(void* const* d_in, const int* in_sizes, int n_in,
                              void* d_out, int out_size) {
    (void)in_sizes; (void)n_in; (void)out_size;
    const float* X   = (const float*)d_in[0];
    const float* adj = (const float*)d_in[1];
    const float* W1  = (const float*)d_in[2];
    const float* b1  = (const float*)d_in[3];
    const float* W2  = (const float*)d_in[4];
    const float* b2  = (const float*)d_in[5];
    const float* W3  = (const float*)d_in[6];
    const float* b3  = (const float*)d_in[7];
    float* out = (float*)d_out;

    cudaFuncSetAttribute(k_small, cudaFuncAttributeMaxDynamicSharedMemorySize, SMALL_SMEM);
    cudaFuncSetAttribute(k_big,   cudaFuncAttributeMaxDynamicSharedMemorySize, BIG_SMEM);

    k_prep<<<NB * NN, 256>>>(adj);
    k_roundW<<<(3 * FD * FD) / 256, 256>>>(W1, W2, W3);

    const float* biases[3] = {b1, b2, b3};
    for (int l = 0; l < 3; l++) {
        k_small<<<16384 / 128, NT, SMALL_SMEM>>>(X, biases[l], l);
        k_big<<<dim3(NN / 128, NB), 256, BIG_SMEM>>>(out, l);
    }
}